// round 1
// baseline (speedup 1.0000x reference)
#include <cuda_runtime.h>

// Problem shape (fixed by the dataset)
#define BB 4
#define CC 32
#define HH 64
#define WW 64
#define HWW (HH * WW)      // 4096
#define NW 64

#define THREADS 256
#define PIXPT 4            // pixels per thread
#define PIX_PER_BLOCK (THREADS * PIXPT)              // 1024
#define BLOCKS_PER_SLICE (HWW / PIX_PER_BLOCK)       // 4
#define GRID (BB * CC * BLOCKS_PER_SLICE)            // 512

__device__ __forceinline__ float ex2f(float x) {
    float y;
    asm("ex2.approx.ftz.f32 %0, %1;" : "=f"(y) : "f"(x));
    return y;
}

__global__ __launch_bounds__(THREADS)
void cplx_rbf_kernel(const float* __restrict__ xr,
                     const float* __restrict__ xi,
                     const float* __restrict__ wr,
                     const float* __restrict__ wi,
                     const float* __restrict__ br,
                     const float* __restrict__ bi,
                     const float* __restrict__ mur,
                     const float* __restrict__ mui,
                     const float* __restrict__ stddev,
                     float* __restrict__ out)
{
    __shared__ float s_mur[NW];
    __shared__ float s_mui[NW];
    __shared__ float s_negc[NW];   // -log2(e) / (2*stddev_k)
    __shared__ float s_wr[NW];
    __shared__ float s_wi[NW];

    const int slice  = blockIdx.x / BLOCKS_PER_SLICE;   // b*C + c
    const int blk_in = blockIdx.x % BLOCKS_PER_SLICE;
    const int c      = slice % CC;
    const int tid    = threadIdx.x;

    if (tid < NW) {
        s_mur[tid]  = mur[tid];
        s_mui[tid]  = mui[tid];
        s_negc[tid] = -1.4426950408889634f / (2.0f * stddev[tid]);
        s_wr[tid]   = wr[c * NW + tid];
        s_wi[tid]   = wi[c * NW + tid];
    }
    __syncthreads();

    const int base = slice * HWW + blk_in * PIX_PER_BLOCK + tid * PIXPT;

    const float4 xr4 = *reinterpret_cast<const float4*>(xr + base);
    const float4 xi4 = *reinterpret_cast<const float4*>(xi + base);

    float pxr[PIXPT] = {xr4.x, xr4.y, xr4.z, xr4.w};
    float pxi[PIXPT] = {xi4.x, xi4.y, xi4.z, xi4.w};
    float sr[PIXPT]  = {0.f, 0.f, 0.f, 0.f};
    float si[PIXPT]  = {0.f, 0.f, 0.f, 0.f};

    #pragma unroll 16
    for (int k = 0; k < NW; ++k) {
        const float mr  = s_mur[k];
        const float mi  = s_mui[k];
        const float nc  = s_negc[k];
        const float wkr = s_wr[k];
        const float wki = s_wi[k];
        #pragma unroll
        for (int p = 0; p < PIXPT; ++p) {
            const float dr = pxr[p] - mr;
            const float di = pxi[p] - mi;
            const float e  = ex2f(fmaf(di, di, dr * dr) * nc);
            sr[p] = fmaf(e, wkr, sr[p]);
            si[p] = fmaf(e, wki, si[p]);
        }
    }

    const float brc = br[c];
    const float bic = bi[c];

    // Output layout (B,C,H,W,2): interleaved real/imag
    float4 o0, o1;
    o0.x = sr[0] + brc; o0.y = si[0] + bic;
    o0.z = sr[1] + brc; o0.w = si[1] + bic;
    o1.x = sr[2] + brc; o1.y = si[2] + bic;
    o1.z = sr[3] + brc; o1.w = si[3] + bic;

    float* op = out + (size_t)base * 2;
    *reinterpret_cast<float4*>(op)     = o0;
    *reinterpret_cast<float4*>(op + 4) = o1;
}

extern "C" void kernel_launch(void* const* d_in, const int* in_sizes, int n_in,
                              void* d_out, int out_size)
{
    const float* xr     = (const float*)d_in[0];
    const float* xi     = (const float*)d_in[1];
    const float* wr     = (const float*)d_in[2];
    const float* wi     = (const float*)d_in[3];
    const float* br     = (const float*)d_in[4];
    const float* bi     = (const float*)d_in[5];
    const float* mur    = (const float*)d_in[6];
    const float* mui    = (const float*)d_in[7];
    const float* sd     = (const float*)d_in[8];
    float* out          = (float*)d_out;

    cplx_rbf_kernel<<<GRID, THREADS>>>(xr, xi, wr, wi, br, bi, mur, mui, sd, out);
}

// round 2
// speedup vs baseline: 1.0934x; 1.0934x over previous
#include <cuda_runtime.h>

// Problem shape (fixed by the dataset)
#define BB 4
#define CC 32
#define HH 64
#define WW 64
#define HWW (HH * WW)      // 4096
#define NW 64

#define THREADS 256
#define PIXPT 4            // pixels per thread (2 f32x2 pairs)
#define PIX_PER_BLOCK (THREADS * PIXPT)              // 1024
#define BLOCKS_PER_SLICE (HWW / PIX_PER_BLOCK)       // 4
#define GRID (BB * CC * BLOCKS_PER_SLICE)            // 512

typedef unsigned long long u64;

__device__ __forceinline__ float ex2f(float x) {
    float y;
    asm("ex2.approx.ftz.f32 %0, %1;" : "=f"(y) : "f"(x));
    return y;
}
__device__ __forceinline__ u64 pack2(float lo, float hi) {
    u64 r; asm("mov.b64 %0, {%1, %2};" : "=l"(r) : "f"(lo), "f"(hi)); return r;
}
__device__ __forceinline__ void unpack2(u64 v, float& lo, float& hi) {
    asm("mov.b64 {%0, %1}, %2;" : "=f"(lo), "=f"(hi) : "l"(v));
}
__device__ __forceinline__ u64 fma2(u64 a, u64 b, u64 c) {
    u64 r; asm("fma.rn.f32x2 %0, %1, %2, %3;" : "=l"(r) : "l"(a), "l"(b), "l"(c)); return r;
}
__device__ __forceinline__ u64 mul2(u64 a, u64 b) {
    u64 r; asm("mul.rn.f32x2 %0, %1, %2;" : "=l"(r) : "l"(a), "l"(b)); return r;
}

__global__ __launch_bounds__(THREADS)
void cplx_rbf_kernel(const float* __restrict__ xr,
                     const float* __restrict__ xi,
                     const float* __restrict__ wr,
                     const float* __restrict__ wi,
                     const float* __restrict__ br,
                     const float* __restrict__ bi,
                     const float* __restrict__ mur,
                     const float* __restrict__ mui,
                     const float* __restrict__ stddev,
                     float* __restrict__ out)
{
    // Pre-duplicated (v,v) f32x2 constants: exponent = ka*q + kb*x + kc*y + kd
    __shared__ u64 s_ka[NW];   // nc
    __shared__ u64 s_kb[NW];   // -2*nc*mr
    __shared__ u64 s_kc[NW];   // -2*nc*mi
    __shared__ u64 s_kd[NW];   // nc*(mr^2+mi^2)
    __shared__ u64 s_wr[NW];
    __shared__ u64 s_wi[NW];

    const int slice  = blockIdx.x / BLOCKS_PER_SLICE;   // b*C + c
    const int blk_in = blockIdx.x % BLOCKS_PER_SLICE;
    const int c      = slice % CC;
    const int tid    = threadIdx.x;

    if (tid < NW) {
        const float mr = mur[tid];
        const float mi = mui[tid];
        const float nc = -1.4426950408889634f / (2.0f * stddev[tid]);  // -log2(e)/(2*sd)
        s_ka[tid] = pack2(nc, nc);
        const float kb = -2.0f * nc * mr;
        const float kc = -2.0f * nc * mi;
        const float kd = nc * (mr * mr + mi * mi);
        s_kb[tid] = pack2(kb, kb);
        s_kc[tid] = pack2(kc, kc);
        s_kd[tid] = pack2(kd, kd);
        const float wkr = wr[c * NW + tid];
        const float wki = wi[c * NW + tid];
        s_wr[tid] = pack2(wkr, wkr);
        s_wi[tid] = pack2(wki, wki);
    }
    __syncthreads();

    const int base = slice * HWW + blk_in * PIX_PER_BLOCK + tid * PIXPT;

    const float4 xr4 = *reinterpret_cast<const float4*>(xr + base);
    const float4 xi4 = *reinterpret_cast<const float4*>(xi + base);

    // Pixel pairs packed as f32x2
    u64 xrd0 = pack2(xr4.x, xr4.y);
    u64 xrd1 = pack2(xr4.z, xr4.w);
    u64 xid0 = pack2(xi4.x, xi4.y);
    u64 xid1 = pack2(xi4.z, xi4.w);
    // q = xr^2 + xi^2 per pixel, packed
    u64 qd0 = fma2(xrd0, xrd0, mul2(xid0, xid0));
    u64 qd1 = fma2(xrd1, xrd1, mul2(xid1, xid1));

    u64 srd0 = 0ull, srd1 = 0ull, sid0 = 0ull, sid1 = 0ull;  // +0.0f,+0.0f packed

    #pragma unroll 16
    for (int k = 0; k < NW; ++k) {
        const u64 ka = s_ka[k];
        const u64 kb = s_kb[k];
        const u64 kc = s_kc[k];
        const u64 kd = s_kd[k];
        const u64 wkr = s_wr[k];
        const u64 wki = s_wi[k];

        // exponent (base-2) for both pairs: 3 packed FFMAs each
        u64 t0 = fma2(ka, qd0, kd);
        t0 = fma2(kb, xrd0, t0);
        t0 = fma2(kc, xid0, t0);
        u64 t1 = fma2(ka, qd1, kd);
        t1 = fma2(kb, xrd1, t1);
        t1 = fma2(kc, xid1, t1);

        float a0, a1, b0, b1;
        unpack2(t0, a0, a1);
        unpack2(t1, b0, b1);
        const u64 e0 = pack2(ex2f(a0), ex2f(a1));
        const u64 e1 = pack2(ex2f(b0), ex2f(b1));

        srd0 = fma2(e0, wkr, srd0);
        sid0 = fma2(e0, wki, sid0);
        srd1 = fma2(e1, wkr, srd1);
        sid1 = fma2(e1, wki, sid1);
    }

    const float brc = br[c];
    const float bic = bi[c];

    float sr0, sr1, sr2, sr3, si0, si1, si2, si3;
    unpack2(srd0, sr0, sr1);
    unpack2(srd1, sr2, sr3);
    unpack2(sid0, si0, si1);
    unpack2(sid1, si2, si3);

    // Output layout (B,C,H,W,2): interleaved real/imag
    float4 o0, o1;
    o0.x = sr0 + brc; o0.y = si0 + bic;
    o0.z = sr1 + brc; o0.w = si1 + bic;
    o1.x = sr2 + brc; o1.y = si2 + bic;
    o1.z = sr3 + brc; o1.w = si3 + bic;

    float* op = out + (size_t)base * 2;
    *reinterpret_cast<float4*>(op)     = o0;
    *reinterpret_cast<float4*>(op + 4) = o1;
}

extern "C" void kernel_launch(void* const* d_in, const int* in_sizes, int n_in,
                              void* d_out, int out_size)
{
    const float* xr  = (const float*)d_in[0];
    const float* xi  = (const float*)d_in[1];
    const float* wr  = (const float*)d_in[2];
    const float* wi  = (const float*)d_in[3];
    const float* br  = (const float*)d_in[4];
    const float* bi  = (const float*)d_in[5];
    const float* mur = (const float*)d_in[6];
    const float* mui = (const float*)d_in[7];
    const float* sd  = (const float*)d_in[8];
    float* out       = (float*)d_out;

    cplx_rbf_kernel<<<GRID, THREADS>>>(xr, xi, wr, wi, br, bi, mur, mui, sd, out);
}

// round 4
// speedup vs baseline: 1.2907x; 1.1805x over previous
#include <cuda_runtime.h>

// Problem shape (fixed by the dataset)
#define BB 4
#define CC 32
#define HH 64
#define WW 64
#define HWW (HH * WW)      // 4096
#define NW 64

#define THREADS 128
#define PIXPT 4            // pixels per thread (2 f32x2 pairs)
#define PIX_PER_BLOCK (THREADS * PIXPT)              // 512
#define BLOCKS_PER_SLICE (HWW / PIX_PER_BLOCK)       // 8
#define GRID (BB * CC * BLOCKS_PER_SLICE)            // 1024

typedef unsigned long long u64;

__device__ __forceinline__ float ex2f(float x) {
    float y;
    asm("ex2.approx.ftz.f32 %0, %1;" : "=f"(y) : "f"(x));
    return y;
}
__device__ __forceinline__ u64 pack2(float lo, float hi) {
    u64 r; asm("mov.b64 %0, {%1, %2};" : "=l"(r) : "f"(lo), "f"(hi)); return r;
}
__device__ __forceinline__ void unpack2(u64 v, float& lo, float& hi) {
    asm("mov.b64 {%0, %1}, %2;" : "=f"(lo), "=f"(hi) : "l"(v));
}
__device__ __forceinline__ u64 fma2(u64 a, u64 b, u64 c) {
    u64 r; asm("fma.rn.f32x2 %0, %1, %2, %3;" : "=l"(r) : "l"(a), "l"(b), "l"(c)); return r;
}
__device__ __forceinline__ u64 mul2(u64 a, u64 b) {
    u64 r; asm("mul.rn.f32x2 %0, %1, %2;" : "=l"(r) : "l"(a), "l"(b)); return r;
}

// exponent(base2) = ka*q + kb*x + kc*y   (kd folded into weights)
//   ka = -log2e/(2*sd), kb = -2*ka*mr, kc = -2*ka*mi
//   wr' = wr * 2^(ka*(mr^2+mi^2)),  wi' likewise

__global__ __launch_bounds__(THREADS)
void cplx_rbf_kernel(const float* __restrict__ xr,
                     const float* __restrict__ xi,
                     const float* __restrict__ wr,
                     const float* __restrict__ wi,
                     const float* __restrict__ br,
                     const float* __restrict__ bi,
                     const float* __restrict__ mur,
                     const float* __restrict__ mui,
                     const float* __restrict__ stddev,
                     float* __restrict__ out)
{
    // pre-duplicated (v,v) f32x2 constants, packed for wide LDS
    __shared__ __align__(16) u64 s_kab[NW * 2];  // [2k]=ka  [2k+1]=kb   -> LDS.128
    __shared__ __align__(16) u64 s_kcw[NW * 2];  // [2k]=kc  [2k+1]=wr'  -> LDS.128
    __shared__ u64 s_wi[NW];                     // wi'                  -> LDS.64

    const int slice  = blockIdx.x / BLOCKS_PER_SLICE;   // b*C + c
    const int blk_in = blockIdx.x % BLOCKS_PER_SLICE;
    const int c      = slice % CC;
    const int tid    = threadIdx.x;

    if (tid < NW) {
        const float mr = mur[tid];
        const float mi = mui[tid];
        const float ka = -1.4426950408889634f / (2.0f * stddev[tid]);
        const float kb = -2.0f * ka * mr;
        const float kc = -2.0f * ka * mi;
        const float ew = ex2f(ka * (mr * mr + mi * mi));   // 2^kd
        const float wkr = wr[c * NW + tid] * ew;
        const float wki = wi[c * NW + tid] * ew;
        s_kab[2 * tid]     = pack2(ka, ka);
        s_kab[2 * tid + 1] = pack2(kb, kb);
        s_kcw[2 * tid]     = pack2(kc, kc);
        s_kcw[2 * tid + 1] = pack2(wkr, wkr);
        s_wi[tid]          = pack2(wki, wki);
    }
    __syncthreads();

    const int base = slice * HWW + blk_in * PIX_PER_BLOCK + tid * PIXPT;

    const float4 xr4 = *reinterpret_cast<const float4*>(xr + base);
    const float4 xi4 = *reinterpret_cast<const float4*>(xi + base);

    // pixel pairs packed as f32x2
    const u64 xrd0 = pack2(xr4.x, xr4.y);
    const u64 xrd1 = pack2(xr4.z, xr4.w);
    const u64 xid0 = pack2(xi4.x, xi4.y);
    const u64 xid1 = pack2(xi4.z, xi4.w);
    // q = x^2 + y^2 per pixel
    const u64 qd0 = fma2(xrd0, xrd0, mul2(xid0, xid0));
    const u64 qd1 = fma2(xrd1, xrd1, mul2(xid1, xid1));

    u64 srd0 = 0ull, srd1 = 0ull, sid0 = 0ull, sid1 = 0ull;

    const ulonglong2* kab = reinterpret_cast<const ulonglong2*>(s_kab);
    const ulonglong2* kcw = reinterpret_cast<const ulonglong2*>(s_kcw);

    #pragma unroll 8
    for (int k = 0; k < NW; ++k) {
        const ulonglong2 ab = kab[k];     // LDS.128 broadcast
        const ulonglong2 cw = kcw[k];     // LDS.128 broadcast
        const u64 wki = s_wi[k];          // LDS.64  broadcast
        const u64 ka = ab.x, kb = ab.y, kc = cw.x, wkr = cw.y;

        u64 t0 = fma2(kb, xrd0, mul2(ka, qd0));
        t0 = fma2(kc, xid0, t0);
        u64 t1 = fma2(kb, xrd1, mul2(ka, qd1));
        t1 = fma2(kc, xid1, t1);

        float a0, a1, b0, b1;
        unpack2(t0, a0, a1);
        unpack2(t1, b0, b1);
        const u64 e0 = pack2(ex2f(a0), ex2f(a1));
        const u64 e1 = pack2(ex2f(b0), ex2f(b1));

        srd0 = fma2(e0, wkr, srd0);
        sid0 = fma2(e0, wki, sid0);
        srd1 = fma2(e1, wkr, srd1);
        sid1 = fma2(e1, wki, sid1);
    }

    const float brc = br[c];
    const float bic = bi[c];

    float sr0, sr1, sr2, sr3, si0, si1, si2, si3;
    unpack2(srd0, sr0, sr1);
    unpack2(srd1, sr2, sr3);
    unpack2(sid0, si0, si1);
    unpack2(sid1, si2, si3);

    // Output layout (B,C,H,W,2): interleaved real/imag
    float4 o0, o1;
    o0.x = sr0 + brc; o0.y = si0 + bic;
    o0.z = sr1 + brc; o0.w = si1 + bic;
    o1.x = sr2 + brc; o1.y = si2 + bic;
    o1.z = sr3 + brc; o1.w = si3 + bic;

    float* op = out + (size_t)base * 2;
    *reinterpret_cast<float4*>(op)     = o0;
    *reinterpret_cast<float4*>(op + 4) = o1;
}

extern "C" void kernel_launch(void* const* d_in, const int* in_sizes, int n_in,
                              void* d_out, int out_size)
{
    const float* xr  = (const float*)d_in[0];
    const float* xi  = (const float*)d_in[1];
    const float* wr  = (const float*)d_in[2];
    const float* wi  = (const float*)d_in[3];
    const float* br  = (const float*)d_in[4];
    const float* bi  = (const float*)d_in[5];
    const float* mur = (const float*)d_in[6];
    const float* mui = (const float*)d_in[7];
    const float* sd  = (const float*)d_in[8];
    float* out       = (float*)d_out;

    cplx_rbf_kernel<<<GRID, THREADS>>>(xr, xi, wr, wi, br, bi, mur, mui, sd, out);
}